// round 1
// baseline (speedup 1.0000x reference)
#include <cuda_runtime.h>
#include <math.h>
#include <stdint.h>

// Problem constants
#define BB 2
#define LL 2048
#define DD 2048
#define NHEADS 16
#define KHEADS 8
#define HDIM 128
#define TOK (BB * LL)        // 4096
#define EPSV 1e-6f

// ---------------------------------------------------------------------------
// Scratch (device globals — no runtime allocation allowed)
// ---------------------------------------------------------------------------
__device__ float g_q[(size_t)TOK * NHEADS * HDIM];   // 33.5 MB  [token][n*128+h]
__device__ float g_k[(size_t)TOK * KHEADS * HDIM];   // 16.8 MB  [token][k*128+h]
__device__ float g_v[(size_t)TOK * KHEADS * HDIM];   // 16.8 MB
__device__ float g_o[(size_t)TOK * NHEADS * HDIM];   // 33.5 MB  attention output

// ---------------------------------------------------------------------------
// SGEMM body: 128x128 tile, BK=8, 256 threads, 8x8 per-thread microtile
// A: [M x K] row-major (lda), B: [K x N] row-major (ldb), C row-major (ldc)
// Block computes C[128 x 128] at given base pointers. All dims multiple of tile.
// ---------------------------------------------------------------------------
__device__ __forceinline__ void gemm_body_128(
    const float* __restrict__ A, int lda,
    const float* __restrict__ Bm, int ldb,
    float* __restrict__ C, int ldc, int Kdim)
{
    __shared__ float As[8][128];
    __shared__ float Bs[8][128];

    const int tid = threadIdx.x;
    const int tx  = tid & 15;      // 0..15 -> 8 cols each
    const int ty  = tid >> 4;      // 0..15 -> 8 rows each

    // A load mapping: float4 per thread, row = tid/2, col4 = (tid&1)*4
    const int ar = tid >> 1;
    const int ac = (tid & 1) * 4;
    // B load mapping: row = tid/32, col4 = (tid&31)*4
    const int br = tid >> 5;
    const int bc = (tid & 31) * 4;

    float acc[8][8];
#pragma unroll
    for (int i = 0; i < 8; i++)
#pragma unroll
        for (int j = 0; j < 8; j++) acc[i][j] = 0.f;

    for (int k0 = 0; k0 < Kdim; k0 += 8) {
        float4 a4 = *(const float4*)&A[(size_t)ar * lda + k0 + ac];
        As[ac + 0][ar] = a4.x;
        As[ac + 1][ar] = a4.y;
        As[ac + 2][ar] = a4.z;
        As[ac + 3][ar] = a4.w;
        *(float4*)&Bs[br][bc] = *(const float4*)&Bm[(size_t)(k0 + br) * ldb + bc];
        __syncthreads();

#pragma unroll
        for (int k = 0; k < 8; k++) {
            float ra[8], rb[8];
            *(float4*)&ra[0] = *(const float4*)&As[k][ty * 8];
            *(float4*)&ra[4] = *(const float4*)&As[k][ty * 8 + 4];
            *(float4*)&rb[0] = *(const float4*)&Bs[k][tx * 8];
            *(float4*)&rb[4] = *(const float4*)&Bs[k][tx * 8 + 4];
#pragma unroll
            for (int i = 0; i < 8; i++)
#pragma unroll
                for (int j = 0; j < 8; j++)
                    acc[i][j] += ra[i] * rb[j];
        }
        __syncthreads();
    }

#pragma unroll
    for (int i = 0; i < 8; i++) {
        float* crow = &C[(size_t)(ty * 8 + i) * ldc + tx * 8];
        *(float4*)&crow[0] = make_float4(acc[i][0], acc[i][1], acc[i][2], acc[i][3]);
        *(float4*)&crow[4] = make_float4(acc[i][4], acc[i][5], acc[i][6], acc[i][7]);
    }
}

// ---------------------------------------------------------------------------
// Kernel 1: fused QKV projection.
// X [4096 x 2048] @ {wq [2048 x 2048], wk [2048 x 1024], wv [2048 x 1024]}
// grid.x selects output column tile across the concatenated [q|k|v] columns.
// ---------------------------------------------------------------------------
__global__ void __launch_bounds__(256) qkv_gemm_kernel(
    const float* __restrict__ X,
    const float* __restrict__ wq,
    const float* __restrict__ wk,
    const float* __restrict__ wv)
{
    const int bx = blockIdx.x;   // 0..31 (16 q tiles, 8 k tiles, 8 v tiles)
    const int by = blockIdx.y;   // 0..31 row tiles

    const float* W;
    float* C;
    int ldw, col0;
    if (bx < 16)      { W = wq; C = g_q; ldw = NHEADS * HDIM; col0 = bx * 128; }
    else if (bx < 24) { W = wk; C = g_k; ldw = KHEADS * HDIM; col0 = (bx - 16) * 128; }
    else              { W = wv; C = g_v; ldw = KHEADS * HDIM; col0 = (bx - 24) * 128; }

    gemm_body_128(X + (size_t)by * 128 * DD, DD,
                  W + col0, ldw,
                  C + (size_t)by * 128 * ldw + col0, ldw, DD);
}

// ---------------------------------------------------------------------------
// Kernel 2: RMSNorm + RoPE over q and k head vectors. One warp per 128-vector.
// Lanes 0..15 hold elements 0..63 (first half), lanes 16..31 hold 64..127.
// ---------------------------------------------------------------------------
__global__ void __launch_bounds__(256) norm_rope_kernel(
    const int* __restrict__ pos_ids,
    const float* __restrict__ q_norm_w,
    const float* __restrict__ k_norm_w)
{
    const int warp = (blockIdx.x * blockDim.x + threadIdx.x) >> 5;
    const int lane = threadIdx.x & 31;
    const int NQ = TOK * NHEADS;

    float* vec;
    const float* w;
    int token;
    if (warp < NQ) {
        vec = g_q + (size_t)warp * HDIM;
        token = warp / NHEADS;
        w = q_norm_w;
    } else {
        const int kv = warp - NQ;
        if (kv >= TOK * KHEADS) return;
        vec = g_k + (size_t)kv * HDIM;
        token = kv / KHEADS;
        w = k_norm_w;
    }
    const int pos = pos_ids[token];

    // load 4 contiguous elements per lane
    float4 x4 = *(const float4*)&vec[lane * 4];
    float ss = x4.x * x4.x + x4.y * x4.y + x4.z * x4.z + x4.w * x4.w;
#pragma unroll
    for (int m = 16; m; m >>= 1) ss += __shfl_xor_sync(0xffffffffu, ss, m);
    const float rinv = rsqrtf(ss * (1.0f / HDIM) + EPSV);

    float4 w4 = *(const float4*)&w[lane * 4];
    float n0 = x4.x * w4.x * rinv;
    float n1 = x4.y * w4.y * rinv;
    float n2 = x4.z * w4.z * rinv;
    float n3 = x4.w * w4.w * rinv;

    // exchange with rope partner (element e <-> e+64, i.e. lane xor 16)
    float p0 = __shfl_xor_sync(0xffffffffu, n0, 16);
    float p1 = __shfl_xor_sync(0xffffffffu, n1, 16);
    float p2 = __shfl_xor_sync(0xffffffffu, n2, 16);
    float p3 = __shfl_xor_sync(0xffffffffu, n3, 16);

    const bool firsthalf = lane < 16;
    const int pbase = (lane & 15) * 4;
    const float fpos = (float)pos;
    // log2(1e6)
    const double L2T = 19.931568569324174;

    float nv[4] = {n0, n1, n2, n3};
    float pv[4] = {p0, p1, p2, p3};
    float res[4];
#pragma unroll
    for (int j = 0; j < 4; j++) {
        const int p = pbase + j;
        const float inv_ts = exp2f((float)(-(double)p * L2T / 64.0));
        const float ang = fpos * inv_ts;
        float sv, cv;
        sincosf(ang, &sv, &cv);
        res[j] = firsthalf ? (nv[j] * cv - pv[j] * sv)
                           : (nv[j] * cv + pv[j] * sv);
    }
    *(float4*)&vec[lane * 4] = make_float4(res[0], res[1], res[2], res[3]);
}

// ---------------------------------------------------------------------------
// Kernel 3: causal flash attention, fp32.
// Block = (m-tile of 64 q rows, head n, batch b). 256 threads (16x16),
// 4x4 per-thread score microtile, online softmax, acc[4][8] output microtile.
// SMEM: Qt [128][64] transposed (pre-scaled), Kt [128][64] transposed,
//       Vs [64][128] natural, Ps [64][68] aliases Kt.
// ---------------------------------------------------------------------------
#define FLASH_SMEM_FLOATS (3 * 128 * 64)
#define FLASH_SMEM_BYTES  (FLASH_SMEM_FLOATS * 4)

extern __shared__ float fl_smem[];

__global__ void __launch_bounds__(256) flash_kernel()
{
    float* Qt = fl_smem;                 // [128][64]
    float* Kt = fl_smem + 128 * 64;      // [128][64]
    float* Vs = fl_smem + 2 * 128 * 64;  // [64][128]
    float* Ps = Kt;                      // [64][68] alias (64*68=4352 <= 8192)

    const int mt = blockIdx.x;           // 0..31 m-tile
    const int n  = blockIdx.y;           // head
    const int b  = blockIdx.z;
    const int kvh = n >> 1;              // GQA: q head n -> kv head n/2
    const int m0 = mt * 64;

    const int tid = threadIdx.x;
    const int tx = tid & 15;
    const int ty = tid >> 4;

    const float scale = 0.08838834764831845f;  // 128^-0.5

    // Load Q tile transposed & pre-scaled. Lane mapping: r fast (conflict-free STS)
    {
        const float* qbase = &g_q[((size_t)(b * LL + m0)) * (NHEADS * HDIM) + n * HDIM];
#pragma unroll
        for (int u = tid; u < 64 * 32; u += 256) {
            const int r = u & 63;
            const int h = (u >> 6) * 4;
            float4 v = *(const float4*)&qbase[(size_t)r * (NHEADS * HDIM) + h];
            Qt[(h + 0) * 64 + r] = v.x * scale;
            Qt[(h + 1) * 64 + r] = v.y * scale;
            Qt[(h + 2) * 64 + r] = v.z * scale;
            Qt[(h + 3) * 64 + r] = v.w * scale;
        }
    }

    float m_i[4], l_i[4], acc[4][8];
#pragma unroll
    for (int i = 0; i < 4; i++) {
        m_i[i] = -1e30f;
        l_i[i] = 0.f;
#pragma unroll
        for (int j = 0; j < 8; j++) acc[i][j] = 0.f;
    }

    const int ntiles = mt + 1;
    for (int st = 0; st < ntiles; st++) {
        const int s0 = st * 64;
        __syncthreads();  // prev-iter AV done (and Q load done on first iter)

        // Load K transposed (r-fast mapping) and V natural (h-fast mapping)
        {
            const float* kbase = &g_k[((size_t)(b * LL + s0)) * (KHEADS * HDIM) + kvh * HDIM];
#pragma unroll
            for (int u = tid; u < 64 * 32; u += 256) {
                const int r = u & 63;
                const int h = (u >> 6) * 4;
                float4 v = *(const float4*)&kbase[(size_t)r * (KHEADS * HDIM) + h];
                Kt[(h + 0) * 64 + r] = v.x;
                Kt[(h + 1) * 64 + r] = v.y;
                Kt[(h + 2) * 64 + r] = v.z;
                Kt[(h + 3) * 64 + r] = v.w;
            }
            const float* vbase = &g_v[((size_t)(b * LL + s0)) * (KHEADS * HDIM) + kvh * HDIM];
#pragma unroll
            for (int u = tid; u < 64 * 32; u += 256) {
                const int r = u >> 5;
                const int h = (u & 31) * 4;
                *(float4*)&Vs[r * 128 + h] = *(const float4*)&vbase[(size_t)r * (KHEADS * HDIM) + h];
            }
        }
        __syncthreads();

        // S = Q K^T (per-thread 4x4)
        float s[4][4];
#pragma unroll
        for (int i = 0; i < 4; i++)
#pragma unroll
            for (int j = 0; j < 4; j++) s[i][j] = 0.f;

#pragma unroll 4
        for (int h = 0; h < 128; h++) {
            float4 qv = *(const float4*)&Qt[h * 64 + ty * 4];
            float4 kv = *(const float4*)&Kt[h * 64 + tx * 4];
            const float qa[4] = {qv.x, qv.y, qv.z, qv.w};
            const float ka[4] = {kv.x, kv.y, kv.z, kv.w};
#pragma unroll
            for (int i = 0; i < 4; i++)
#pragma unroll
                for (int j = 0; j < 4; j++)
                    s[i][j] += qa[i] * ka[j];
        }

        // causal mask: only the diagonal tile needs it (s0 == m0 there)
        if (st == mt) {
#pragma unroll
            for (int i = 0; i < 4; i++)
#pragma unroll
                for (int j = 0; j < 4; j++)
                    if (tx * 4 + j > ty * 4 + i) s[i][j] = -1e30f;
        }

        // online softmax update
        float p[4][4];
#pragma unroll
        for (int i = 0; i < 4; i++) {
            float tm = fmaxf(fmaxf(s[i][0], s[i][1]), fmaxf(s[i][2], s[i][3]));
            tm = fmaxf(tm, __shfl_xor_sync(0xffffffffu, tm, 1));
            tm = fmaxf(tm, __shfl_xor_sync(0xffffffffu, tm, 2));
            tm = fmaxf(tm, __shfl_xor_sync(0xffffffffu, tm, 4));
            tm = fmaxf(tm, __shfl_xor_sync(0xffffffffu, tm, 8));
            const float mn = fmaxf(m_i[i], tm);
            const float corr = __expf(m_i[i] - mn);
            m_i[i] = mn;
            float rs = 0.f;
#pragma unroll
            for (int j = 0; j < 4; j++) {
                p[i][j] = __expf(s[i][j] - mn);
                rs += p[i][j];
            }
            rs += __shfl_xor_sync(0xffffffffu, rs, 1);
            rs += __shfl_xor_sync(0xffffffffu, rs, 2);
            rs += __shfl_xor_sync(0xffffffffu, rs, 4);
            rs += __shfl_xor_sync(0xffffffffu, rs, 8);
            l_i[i] = l_i[i] * corr + rs;
#pragma unroll
            for (int jj = 0; jj < 8; jj++) acc[i][jj] *= corr;
        }

        __syncthreads();  // all threads done reading Kt before Ps overwrites it
#pragma unroll
        for (int i = 0; i < 4; i++)
#pragma unroll
            for (int j = 0; j < 4; j++)
                Ps[(ty * 4 + i) * 68 + tx * 4 + j] = p[i][j];
        __syncthreads();

        // O += P @ V   (acc rows ty*4+i, h-cols tx*8..tx*8+7)
#pragma unroll 4
        for (int c = 0; c < 64; c++) {
            float4 v0 = *(const float4*)&Vs[c * 128 + tx * 8];
            float4 v1 = *(const float4*)&Vs[c * 128 + tx * 8 + 4];
#pragma unroll
            for (int i = 0; i < 4; i++) {
                const float pc = Ps[(ty * 4 + i) * 68 + c];
                acc[i][0] += pc * v0.x;
                acc[i][1] += pc * v0.y;
                acc[i][2] += pc * v0.z;
                acc[i][3] += pc * v0.w;
                acc[i][4] += pc * v1.x;
                acc[i][5] += pc * v1.y;
                acc[i][6] += pc * v1.z;
                acc[i][7] += pc * v1.w;
            }
        }
    }

    // finalize: divide by l, write to g_o
#pragma unroll
    for (int i = 0; i < 4; i++) {
        const float inv = 1.0f / l_i[i];
        const int r = m0 + ty * 4 + i;
        float* dst = &g_o[((size_t)(b * LL + r)) * (NHEADS * HDIM) + n * HDIM + tx * 8];
        *(float4*)&dst[0] = make_float4(acc[i][0] * inv, acc[i][1] * inv,
                                        acc[i][2] * inv, acc[i][3] * inv);
        *(float4*)&dst[4] = make_float4(acc[i][4] * inv, acc[i][5] * inv,
                                        acc[i][6] * inv, acc[i][7] * inv);
    }
}

// ---------------------------------------------------------------------------
// Kernel 4: output projection.  g_o [4096 x 2048] @ wo [2048 x 2048] -> out
// (wo is [N,H,D] contiguous == [N*H, D] row-major, exactly what we need)
// ---------------------------------------------------------------------------
__global__ void __launch_bounds__(256) out_gemm_kernel(
    const float* __restrict__ wo, float* __restrict__ out)
{
    const int bx = blockIdx.x;  // 0..15 col tiles (D = 2048)
    const int by = blockIdx.y;  // 0..31 row tiles
    gemm_body_128(g_o + (size_t)by * 128 * (NHEADS * HDIM), NHEADS * HDIM,
                  wo + bx * 128, DD,
                  out + (size_t)by * 128 * DD + bx * 128, DD, NHEADS * HDIM);
}

// ---------------------------------------------------------------------------
// Launch
// ---------------------------------------------------------------------------
extern "C" void kernel_launch(void* const* d_in, const int* in_sizes, int n_in,
                              void* d_out, int out_size)
{
    const float* x   = (const float*)d_in[0];
    const int*   pos = (const int*)d_in[1];
    // d_in[2] = attn_mask (causal tril) — implied analytically, unused
    const float* wq  = (const float*)d_in[3];
    const float* wk  = (const float*)d_in[4];
    const float* wv  = (const float*)d_in[5];
    const float* wo  = (const float*)d_in[6];
    const float* qnw = (const float*)d_in[7];
    const float* knw = (const float*)d_in[8];
    float* out = (float*)d_out;

    // 1. QKV projection
    qkv_gemm_kernel<<<dim3(32, 32), 256>>>(x, wq, wk, wv);

    // 2. RMSNorm + RoPE (one warp per head vector)
    {
        const int nwarps = TOK * NHEADS + TOK * KHEADS;  // 98304
        const int blocks = (nwarps * 32 + 255) / 256;    // 12288
        norm_rope_kernel<<<blocks, 256>>>(pos, qnw, knw);
    }

    // 3. Flash attention
    cudaFuncSetAttribute(flash_kernel,
                         cudaFuncAttributeMaxDynamicSharedMemorySize,
                         FLASH_SMEM_BYTES);
    flash_kernel<<<dim3(LL / 64, NHEADS, BB), 256, FLASH_SMEM_BYTES>>>();

    // 4. Output projection
    out_gemm_kernel<<<dim3(DD / 128, 32), 256>>>(wo, out);
}

// round 3
// speedup vs baseline: 1.6103x; 1.6103x over previous
#include <cuda_runtime.h>
#include <cuda_bf16.h>
#include <math.h>
#include <stdint.h>

// Problem constants
#define BB 2
#define LL 2048
#define DD 2048
#define NHEADS 16
#define KHEADS 8
#define HDIM 128
#define TOK (BB * LL)        // 4096
#define EPSV 1e-6f
#define QKVW 4096            // g_qkv row width (q:0..2047, k:2048..3071, v:3072..4095)

// ---------------------------------------------------------------------------
// Scratch (device globals — no runtime allocation allowed)
// ---------------------------------------------------------------------------
__device__ float g_qkv[(size_t)TOK * QKVW];                         // 67 MB
__device__ float g_o[(size_t)TOK * DD];                             // 33.5 MB
__device__ __align__(16) __nv_bfloat16 g_xhi[(size_t)TOK * DD];     // 16.8 MB
__device__ __align__(16) __nv_bfloat16 g_xlo[(size_t)TOK * DD];
__device__ __align__(16) __nv_bfloat16 g_ohi[(size_t)TOK * DD];
__device__ __align__(16) __nv_bfloat16 g_olo[(size_t)TOK * DD];
__device__ __align__(16) __nv_bfloat16 g_wthi[(size_t)QKVW * DD];   // [n][k] transposed qkv weights
__device__ __align__(16) __nv_bfloat16 g_wtlo[(size_t)QKVW * DD];
__device__ __align__(16) __nv_bfloat16 g_wothi[(size_t)DD * DD];    // [n][k] transposed wo
__device__ __align__(16) __nv_bfloat16 g_wotlo[(size_t)DD * DD];

extern __shared__ char dyn_smem[];

// ---------------------------------------------------------------------------
// PTX helpers (family-portable only: cp.async / ldmatrix / mma.sync)
// ---------------------------------------------------------------------------
__device__ __forceinline__ uint32_t smem_u32(const void* p) {
    uint32_t a;
    asm("{ .reg .u64 t; cvta.to.shared.u64 t, %1; cvt.u32.u64 %0, t; }"
        : "=r"(a) : "l"(p));
    return a;
}

__device__ __forceinline__ void cp16(uint32_t dst, const void* src) {
    asm volatile("cp.async.cg.shared.global [%0], [%1], 16;" :: "r"(dst), "l"(src));
}
#define CP_COMMIT() asm volatile("cp.async.commit_group;" ::: "memory")
#define CP_WAIT(N)  asm volatile("cp.async.wait_group %0;" :: "n"(N) : "memory")

__device__ __forceinline__ void ldsm4(uint32_t* r, uint32_t a) {
    asm volatile("ldmatrix.sync.aligned.m8n8.x4.shared.b16 {%0,%1,%2,%3}, [%4];"
        : "=r"(r[0]), "=r"(r[1]), "=r"(r[2]), "=r"(r[3]) : "r"(a));
}

__device__ __forceinline__ void mma_bf16(float* c, const uint32_t* a, const uint32_t* b) {
    asm volatile(
        "mma.sync.aligned.m16n8k16.row.col.f32.bf16.bf16.f32 "
        "{%0,%1,%2,%3}, {%4,%5,%6,%7}, {%8,%9}, {%0,%1,%2,%3};"
        : "+f"(c[0]), "+f"(c[1]), "+f"(c[2]), "+f"(c[3])
        : "r"(a[0]), "r"(a[1]), "r"(a[2]), "r"(a[3]), "r"(b[0]), "r"(b[1]));
}

// ---------------------------------------------------------------------------
// Conversion kernels
// ---------------------------------------------------------------------------
// fp32 [R][C] row-major -> bf16 hi/lo transposed: dst[(row_off + c)][r], ld=2048
__global__ void __launch_bounds__(256) transpose_convert_kernel(
    const float* __restrict__ src, int R, int C, int row_off, int which)
{
    __shared__ float t[32][33];
    const int c0 = blockIdx.x * 32;
    const int r0 = blockIdx.y * 32;
    const int tx = threadIdx.x;     // 0..31
    const int ty = threadIdx.y;     // 0..7

#pragma unroll
    for (int j = 0; j < 4; j++)
        t[ty + j * 8][tx] = src[(size_t)(r0 + ty + j * 8) * C + c0 + tx];
    __syncthreads();

    __nv_bfloat16* dhi = which ? g_wothi : g_wthi;
    __nv_bfloat16* dlo = which ? g_wotlo : g_wtlo;
#pragma unroll
    for (int j = 0; j < 4; j++) {
        const int i = ty + j * 8;
        const float v = t[tx][i];
        const __nv_bfloat16 h = __float2bfloat16(v);
        const __nv_bfloat16 l = __float2bfloat16(v - __bfloat162float(h));
        const size_t off = (size_t)(row_off + c0 + i) * DD + r0 + tx;
        dhi[off] = h;
        dlo[off] = l;
    }
}

// straight split: mode 0: x -> g_xhi/g_xlo ; mode 1: g_o -> g_ohi/g_olo
__global__ void __launch_bounds__(256) convert_split_kernel(
    const float* __restrict__ src, int mode)
{
    const size_t i = (size_t)blockIdx.x * blockDim.x + threadIdx.x;
    const size_t n4 = (size_t)TOK * DD / 4;
    if (i >= n4) return;
    const float4 v = ((mode == 0) ? (const float4*)src : (const float4*)g_o)[i];
    __nv_bfloat16 h0 = __float2bfloat16(v.x);
    __nv_bfloat16 h1 = __float2bfloat16(v.y);
    __nv_bfloat16 h2 = __float2bfloat16(v.z);
    __nv_bfloat16 h3 = __float2bfloat16(v.w);
    __nv_bfloat162 hp0; hp0.x = h0; hp0.y = h1;
    __nv_bfloat162 hp1; hp1.x = h2; hp1.y = h3;
    __nv_bfloat162 lp0, lp1;
    lp0.x = __float2bfloat16(v.x - __bfloat162float(h0));
    lp0.y = __float2bfloat16(v.y - __bfloat162float(h1));
    lp1.x = __float2bfloat16(v.z - __bfloat162float(h2));
    lp1.y = __float2bfloat16(v.w - __bfloat162float(h3));
    __nv_bfloat162* hi = (__nv_bfloat162*)(mode ? g_ohi : g_xhi);
    __nv_bfloat162* lo = (__nv_bfloat162*)(mode ? g_olo : g_xlo);
    hi[i * 2]     = hp0;
    hi[i * 2 + 1] = hp1;
    lo[i * 2]     = lp0;
    lo[i * 2 + 1] = lp1;
}

// ---------------------------------------------------------------------------
// split-bf16 warp-MMA GEMM: C[M x N] = A[M x K] * B[N x K]^T, fp32 out
//   CTA tile 128x128, BK=32, 8 warps (2m x 4n), warp tile 64x32.
//   3 products per frag: hi*hi + hi*lo + lo*hi (lo*lo dropped).
//   SMEM: per stage {Ahi, Alo, Bhi, Blo} 128 rows x 32 bf16, 80B pitch
//   (pad 16B -> ldmatrix 8-row phases hit distinct banks). 2 stages = 80 KB.
// ---------------------------------------------------------------------------
#define BK 32
#define PITCH 80
#define MAT_BYTES (128 * PITCH)           // 10240
#define STAGE_BYTES (4 * MAT_BYTES)       // 40960
#define GEMM_SMEM_BYTES (2 * STAGE_BYTES) // 81920

__device__ __forceinline__ void prefetch_stage(
    uint32_t sbase,
    const __nv_bfloat16* __restrict__ Ahi, const __nv_bfloat16* __restrict__ Alo,
    const __nv_bfloat16* __restrict__ Bhi, const __nv_bfloat16* __restrict__ Blo,
    int m0, int n0, int k0, int ldA, int ldB, int tid)
{
#pragma unroll
    for (int j = 0; j < 2; j++) {
        const int id = tid * 2 + j;          // 0..511
        const int r = id >> 2;               // row 0..127
        const int c = id & 3;                // 16B chunk 0..3
        const uint32_t soff = r * PITCH + c * 16;
        const size_t ga = (size_t)(m0 + r) * ldA + k0 + c * 8;
        const size_t gb = (size_t)(n0 + r) * ldB + k0 + c * 8;
        cp16(sbase + soff,                 Ahi + ga);
        cp16(sbase + MAT_BYTES + soff,     Alo + ga);
        cp16(sbase + 2 * MAT_BYTES + soff, Bhi + gb);
        cp16(sbase + 3 * MAT_BYTES + soff, Blo + gb);
    }
}

__device__ __forceinline__ void gemm_bf16x3_body(
    const __nv_bfloat16* __restrict__ Ahi, const __nv_bfloat16* __restrict__ Alo,
    const __nv_bfloat16* __restrict__ Bhi, const __nv_bfloat16* __restrict__ Blo,
    float* __restrict__ Cc, int K, int ldA, int ldB, int ldC)
{
    const int tid  = threadIdx.x;           // 256 threads
    const int lane = tid & 31;
    const int wid  = tid >> 5;               // 0..7
    const int wm   = wid & 1;                // 2 m-warps
    const int wn   = wid >> 1;               // 4 n-warps
    const int m0   = blockIdx.y * 128;
    const int n0   = blockIdx.x * 128;
    const uint32_t smem_base = smem_u32(dyn_smem);

    float c[4][4][4];
#pragma unroll
    for (int i = 0; i < 4; i++)
#pragma unroll
        for (int j = 0; j < 4; j++)
#pragma unroll
            for (int k = 0; k < 4; k++) c[i][j][k] = 0.f;

    // ldmatrix lane addressing (byte offsets within a 128x32 tile, 80B pitch)
    // A (x4 -> m16 x k16): row = warp_m*64 + mf*16 + (lane&15), +16B for lanes>=16
    const uint32_t a_lane_off =
        (uint32_t)((wm * 64 + (lane & 15)) * PITCH + (lane >> 4) * 16);
    // B (x4 -> n16 x k16): n = warp_n*32 + nf2*16 + (lane&7) + ((lane>>4)<<3),
    //                      kbyte = ((lane>>3)&1)*16
    const uint32_t b_lane_off =
        (uint32_t)((wn * 32 + (lane & 7) + ((lane >> 4) << 3)) * PITCH +
                   ((lane >> 3) & 1) * 16);

    const int nk = K / BK;    // 64

    prefetch_stage(smem_base, Ahi, Alo, Bhi, Blo, m0, n0, 0, ldA, ldB, tid);
    CP_COMMIT();

    for (int it = 0; it < nk; it++) {
        CP_WAIT(0);
        __syncthreads();   // stage it&1 ready; stage (it+1)&1 reads all done

        if (it + 1 < nk) {
            prefetch_stage(smem_base + ((it + 1) & 1) * STAGE_BYTES,
                           Ahi, Alo, Bhi, Blo, m0, n0, (it + 1) * BK, ldA, ldB, tid);
            CP_COMMIT();
        }

        const uint32_t sA = smem_base + (it & 1) * STAGE_BYTES;
        const uint32_t sB = sA + 2 * MAT_BYTES;

#pragma unroll
        for (int kf = 0; kf < 2; kf++) {
            uint32_t a[2][4][4];   // [split][mf][reg]
            uint32_t b[2][2][4];   // [split][nf2][reg]
#pragma unroll
            for (int mf = 0; mf < 4; mf++) {
                const uint32_t ad = sA + a_lane_off + mf * 16 * PITCH + kf * 32;
                ldsm4(a[0][mf], ad);
                ldsm4(a[1][mf], ad + MAT_BYTES);
            }
#pragma unroll
            for (int nf2 = 0; nf2 < 2; nf2++) {
                const uint32_t bd = sB + b_lane_off + nf2 * 16 * PITCH + kf * 32;
                ldsm4(b[0][nf2], bd);
                ldsm4(b[1][nf2], bd + MAT_BYTES);
            }
#pragma unroll
            for (int mf = 0; mf < 4; mf++)
#pragma unroll
                for (int nf = 0; nf < 4; nf++) {
                    float* cc = c[mf][nf];
                    const uint32_t* bh = &b[0][nf >> 1][(nf & 1) * 2];
                    const uint32_t* bl = &b[1][nf >> 1][(nf & 1) * 2];
                    mma_bf16(cc, a[0][mf], bh);   // hi*hi
                    mma_bf16(cc, a[0][mf], bl);   // hi*lo
                    mma_bf16(cc, a[1][mf], bh);   // lo*hi
                }
        }
    }

    // Epilogue: direct fp32 stores from C fragments
    const int row0 = m0 + wm * 64;
    const int col0 = n0 + wn * 32;
    const int gr = lane >> 2;
    const int gc = (lane & 3) * 2;
#pragma unroll
    for (int mf = 0; mf < 4; mf++)
#pragma unroll
        for (int nf = 0; nf < 4; nf++) {
            float* cc = c[mf][nf];
            const int r = row0 + mf * 16 + gr;
            const int cl = col0 + nf * 8 + gc;
            *(float2*)&Cc[(size_t)r * ldC + cl]       = make_float2(cc[0], cc[1]);
            *(float2*)&Cc[(size_t)(r + 8) * ldC + cl] = make_float2(cc[2], cc[3]);
        }
}

__global__ void __launch_bounds__(256) gemm_qkv_kernel() {
    gemm_bf16x3_body(g_xhi, g_xlo, g_wthi, g_wtlo, g_qkv, DD, DD, DD, QKVW);
}
__global__ void __launch_bounds__(256) gemm_out_kernel(float* __restrict__ out) {
    gemm_bf16x3_body(g_ohi, g_olo, g_wothi, g_wotlo, out, DD, DD, DD, DD);
}

// ---------------------------------------------------------------------------
// RMSNorm + RoPE over q and k head vectors. One warp per 128-vector.
// ---------------------------------------------------------------------------
__global__ void __launch_bounds__(256) norm_rope_kernel(
    const int* __restrict__ pos_ids,
    const float* __restrict__ q_norm_w,
    const float* __restrict__ k_norm_w)
{
    const int warp = (blockIdx.x * blockDim.x + threadIdx.x) >> 5;
    const int lane = threadIdx.x & 31;
    const int NQ = TOK * NHEADS;

    float* vec;
    const float* w;
    int token;
    if (warp < NQ) {
        token = warp / NHEADS;
        vec = g_qkv + (size_t)token * QKVW + (warp % NHEADS) * HDIM;
        w = q_norm_w;
    } else {
        const int kv = warp - NQ;
        if (kv >= TOK * KHEADS) return;
        token = kv / KHEADS;
        vec = g_qkv + (size_t)token * QKVW + 2048 + (kv % KHEADS) * HDIM;
        w = k_norm_w;
    }
    const int pos = pos_ids[token];

    float4 x4 = *(const float4*)&vec[lane * 4];
    float ss = x4.x * x4.x + x4.y * x4.y + x4.z * x4.z + x4.w * x4.w;
#pragma unroll
    for (int m = 16; m; m >>= 1) ss += __shfl_xor_sync(0xffffffffu, ss, m);
    const float rinv = rsqrtf(ss * (1.0f / HDIM) + EPSV);

    float4 w4 = *(const float4*)&w[lane * 4];
    float n0 = x4.x * w4.x * rinv;
    float n1 = x4.y * w4.y * rinv;
    float n2 = x4.z * w4.z * rinv;
    float n3 = x4.w * w4.w * rinv;

    float p0 = __shfl_xor_sync(0xffffffffu, n0, 16);
    float p1 = __shfl_xor_sync(0xffffffffu, n1, 16);
    float p2 = __shfl_xor_sync(0xffffffffu, n2, 16);
    float p3 = __shfl_xor_sync(0xffffffffu, n3, 16);

    const bool firsthalf = lane < 16;
    const int pbase = (lane & 15) * 4;
    const float fpos = (float)pos;
    const double L2T = 19.931568569324174;   // log2(1e6)

    float nv[4] = {n0, n1, n2, n3};
    float pv[4] = {p0, p1, p2, p3};
    float res[4];
#pragma unroll
    for (int j = 0; j < 4; j++) {
        const int p = pbase + j;
        const float inv_ts = exp2f((float)(-(double)p * L2T / 64.0));
        const float ang = fpos * inv_ts;
        float sv, cv;
        sincosf(ang, &sv, &cv);
        res[j] = firsthalf ? (nv[j] * cv - pv[j] * sv)
                           : (nv[j] * cv + pv[j] * sv);
    }
    *(float4*)&vec[lane * 4] = make_float4(res[0], res[1], res[2], res[3]);
}

// ---------------------------------------------------------------------------
// Causal flash attention, fp32 SIMT
// ---------------------------------------------------------------------------
#define FLASH_SMEM_BYTES (3 * 128 * 64 * 4)

__global__ void __launch_bounds__(256) flash_kernel()
{
    float* fs = (float*)dyn_smem;
    float* Qt = fs;                 // [128][64]
    float* Kt = fs + 128 * 64;      // [128][64]
    float* Vs = fs + 2 * 128 * 64;  // [64][128]
    float* Ps = Kt;                 // [64][68] alias

    const int mt = blockIdx.x;
    const int n  = blockIdx.y;
    const int b  = blockIdx.z;
    const int kvh = n >> 1;
    const int m0 = mt * 64;

    const int tid = threadIdx.x;
    const int tx = tid & 15;
    const int ty = tid >> 4;

    const float scale = 0.08838834764831845f;

    {
        const float* qbase = &g_qkv[((size_t)(b * LL + m0)) * QKVW + n * HDIM];
#pragma unroll
        for (int u = tid; u < 64 * 32; u += 256) {
            const int r = u & 63;
            const int h = (u >> 6) * 4;
            float4 v = *(const float4*)&qbase[(size_t)r * QKVW + h];
            Qt[(h + 0) * 64 + r] = v.x * scale;
            Qt[(h + 1) * 64 + r] = v.y * scale;
            Qt[(h + 2) * 64 + r] = v.z * scale;
            Qt[(h + 3) * 64 + r] = v.w * scale;
        }
    }

    float m_i[4], l_i[4], acc[4][8];
#pragma unroll
    for (int i = 0; i < 4; i++) {
        m_i[i] = -1e30f;
        l_i[i] = 0.f;
#pragma unroll
        for (int j = 0; j < 8; j++) acc[i][j] = 0.f;
    }

    const int ntiles = mt + 1;
    for (int st = 0; st < ntiles; st++) {
        const int s0 = st * 64;
        __syncthreads();

        {
            const float* kbase = &g_qkv[((size_t)(b * LL + s0)) * QKVW + 2048 + kvh * HDIM];
#pragma unroll
            for (int u = tid; u < 64 * 32; u += 256) {
                const int r = u & 63;
                const int h = (u >> 6) * 4;
                float4 v = *(const float4*)&kbase[(size_t)r * QKVW + h];
                Kt[(h + 0) * 64 + r] = v.x;
                Kt[(h + 1) * 64 + r] = v.y;
                Kt[(h + 2) * 64 + r] = v.z;
                Kt[(h + 3) * 64 + r] = v.w;
            }
            const float* vbase = &g_qkv[((size_t)(b * LL + s0)) * QKVW + 3072 + kvh * HDIM];
#pragma unroll
            for (int u = tid; u < 64 * 32; u += 256) {
                const int r = u >> 5;
                const int h = (u & 31) * 4;
                *(float4*)&Vs[r * 128 + h] = *(const float4*)&vbase[(size_t)r * QKVW + h];
            }
        }
        __syncthreads();

        float s[4][4];
#pragma unroll
        for (int i = 0; i < 4; i++)
#pragma unroll
            for (int j = 0; j < 4; j++) s[i][j] = 0.f;

#pragma unroll 4
        for (int h = 0; h < 128; h++) {
            float4 qv = *(const float4*)&Qt[h * 64 + ty * 4];
            float4 kv = *(const float4*)&Kt[h * 64 + tx * 4];
            const float qa[4] = {qv.x, qv.y, qv.z, qv.w};
            const float ka[4] = {kv.x, kv.y, kv.z, kv.w};
#pragma unroll
            for (int i = 0; i < 4; i++)
#pragma unroll
                for (int j = 0; j < 4; j++)
                    s[i][j] += qa[i] * ka[j];
        }

        if (st == mt) {
#pragma unroll
            for (int i = 0; i < 4; i++)
#pragma unroll
                for (int j = 0; j < 4; j++)
                    if (tx * 4 + j > ty * 4 + i) s[i][j] = -1e30f;
        }

        float p[4][4];
#pragma unroll
        for (int i = 0; i < 4; i++) {
            float tm = fmaxf(fmaxf(s[i][0], s[i][1]), fmaxf(s[i][2], s[i][3]));
            tm = fmaxf(tm, __shfl_xor_sync(0xffffffffu, tm, 1));
            tm = fmaxf(tm, __shfl_xor_sync(0xffffffffu, tm, 2));
            tm = fmaxf(tm, __shfl_xor_sync(0xffffffffu, tm, 4));
            tm = fmaxf(tm, __shfl_xor_sync(0xffffffffu, tm, 8));
            const float mn = fmaxf(m_i[i], tm);
            const float corr = __expf(m_i[i] - mn);
            m_i[i] = mn;
            float rs = 0.f;
#pragma unroll
            for (int j = 0; j < 4; j++) {
                p[i][j] = __expf(s[i][j] - mn);
                rs += p[i][j];
            }
            rs += __shfl_xor_sync(0xffffffffu, rs, 1);
            rs += __shfl_xor_sync(0xffffffffu, rs, 2);
            rs += __shfl_xor_sync(0xffffffffu, rs, 4);
            rs += __shfl_xor_sync(0xffffffffu, rs, 8);
            l_i[i] = l_i[i] * corr + rs;
#pragma unroll
            for (int jj = 0; jj < 8; jj++) acc[i][jj] *= corr;
        }

        __syncthreads();
#pragma unroll
        for (int i = 0; i < 4; i++)
#pragma unroll
            for (int j = 0; j < 4; j++)
                Ps[(ty * 4 + i) * 68 + tx * 4 + j] = p[i][j];
        __syncthreads();

#pragma unroll 4
        for (int c = 0; c < 64; c++) {
            float4 v0 = *(const float4*)&Vs[c * 128 + tx * 8];
            float4 v1 = *(const float4*)&Vs[c * 128 + tx * 8 + 4];
#pragma unroll
            for (int i = 0; i < 4; i++) {
                const float pc = Ps[(ty * 4 + i) * 68 + c];
                acc[i][0] += pc * v0.x;
                acc[i][1] += pc * v0.y;
                acc[i][2] += pc * v0.z;
                acc[i][3] += pc * v0.w;
                acc[i][4] += pc * v1.x;
                acc[i][5] += pc * v1.y;
                acc[i][6] += pc * v1.z;
                acc[i][7] += pc * v1.w;
            }
        }
    }

#pragma unroll
    for (int i = 0; i < 4; i++) {
        const float inv = 1.0f / l_i[i];
        const int r = m0 + ty * 4 + i;
        float* dst = &g_o[((size_t)(b * LL + r)) * DD + n * HDIM + tx * 8];
        *(float4*)&dst[0] = make_float4(acc[i][0] * inv, acc[i][1] * inv,
                                        acc[i][2] * inv, acc[i][3] * inv);
        *(float4*)&dst[4] = make_float4(acc[i][4] * inv, acc[i][5] * inv,
                                        acc[i][6] * inv, acc[i][7] * inv);
    }
}

// ---------------------------------------------------------------------------
// Launch
// ---------------------------------------------------------------------------
extern "C" void kernel_launch(void* const* d_in, const int* in_sizes, int n_in,
                              void* d_out, int out_size)
{
    const float* x   = (const float*)d_in[0];
    const int*   pos = (const int*)d_in[1];
    // d_in[2] = attn_mask (causal tril) — implied analytically, unused
    const float* wq  = (const float*)d_in[3];
    const float* wk  = (const float*)d_in[4];
    const float* wv  = (const float*)d_in[5];
    const float* wo  = (const float*)d_in[6];
    const float* qnw = (const float*)d_in[7];
    const float* knw = (const float*)d_in[8];
    float* out = (float*)d_out;

    cudaFuncSetAttribute(gemm_qkv_kernel,
                         cudaFuncAttributeMaxDynamicSharedMemorySize, GEMM_SMEM_BYTES);
    cudaFuncSetAttribute(gemm_out_kernel,
                         cudaFuncAttributeMaxDynamicSharedMemorySize, GEMM_SMEM_BYTES);
    cudaFuncSetAttribute(flash_kernel,
                         cudaFuncAttributeMaxDynamicSharedMemorySize, FLASH_SMEM_BYTES);

    // 1. convert weights (transpose + bf16 split)
    transpose_convert_kernel<<<dim3(64, 64), dim3(32, 8)>>>(wq, 2048, 2048, 0, 0);
    transpose_convert_kernel<<<dim3(32, 64), dim3(32, 8)>>>(wk, 2048, 1024, 2048, 0);
    transpose_convert_kernel<<<dim3(32, 64), dim3(32, 8)>>>(wv, 2048, 1024, 3072, 0);
    transpose_convert_kernel<<<dim3(64, 64), dim3(32, 8)>>>(wo, 2048, 2048, 0, 1);

    // 2. split X
    convert_split_kernel<<<(TOK * DD / 4 + 255) / 256, 256>>>(x, 0);

    // 3. QKV projection (tensor cores, mma.sync)
    gemm_qkv_kernel<<<dim3(QKVW / 128, TOK / 128), 256, GEMM_SMEM_BYTES>>>();

    // 4. RMSNorm + RoPE
    {
        const int nwarps = TOK * NHEADS + TOK * KHEADS;
        const int blocks = (nwarps * 32 + 255) / 256;
        norm_rope_kernel<<<blocks, 256>>>(pos, qnw, knw);
    }

    // 5. Flash attention
    flash_kernel<<<dim3(LL / 64, NHEADS, BB), 256, FLASH_SMEM_BYTES>>>();

    // 6. split attention output
    convert_split_kernel<<<(TOK * DD / 4 + 255) / 256, 256>>>(nullptr, 1);

    // 7. output projection (tensor cores, mma.sync)
    gemm_out_kernel<<<dim3(DD / 128, TOK / 128), 256, GEMM_SMEM_BYTES>>>(out);
}

// round 4
// speedup vs baseline: 2.8094x; 1.7446x over previous
#include <cuda_runtime.h>
#include <cuda_bf16.h>
#include <math.h>
#include <stdint.h>

// Problem constants
#define BB 2
#define LL 2048
#define DD 2048
#define NHEADS 16
#define KHEADS 8
#define HDIM 128
#define TOK (BB * LL)        // 4096
#define EPSV 1e-6f
#define QKVW 4096            // g_qkv row width (q:0..2047, k:2048..3071, v:3072..4095)

// ---------------------------------------------------------------------------
// Scratch (device globals — no runtime allocation allowed)
// ---------------------------------------------------------------------------
__device__ float g_qkv[(size_t)TOK * QKVW];                         // 67 MB
__device__ __align__(16) __nv_bfloat16 g_xhi[(size_t)TOK * DD];
__device__ __align__(16) __nv_bfloat16 g_xlo[(size_t)TOK * DD];
__device__ __align__(16) __nv_bfloat16 g_qhi[(size_t)TOK * DD];     // rope'd, pre-scaled q
__device__ __align__(16) __nv_bfloat16 g_qlo[(size_t)TOK * DD];
__device__ __align__(16) __nv_bfloat16 g_khi[(size_t)TOK * KHEADS * HDIM];
__device__ __align__(16) __nv_bfloat16 g_klo[(size_t)TOK * KHEADS * HDIM];
__device__ __align__(16) __nv_bfloat16 g_vhi[(size_t)TOK * KHEADS * HDIM];
__device__ __align__(16) __nv_bfloat16 g_vlo[(size_t)TOK * KHEADS * HDIM];
__device__ __align__(16) __nv_bfloat16 g_ohi[(size_t)TOK * DD];     // attention out
__device__ __align__(16) __nv_bfloat16 g_olo[(size_t)TOK * DD];
__device__ __align__(16) __nv_bfloat16 g_wthi[(size_t)QKVW * DD];   // [n][k] qkv weights
__device__ __align__(16) __nv_bfloat16 g_wtlo[(size_t)QKVW * DD];
__device__ __align__(16) __nv_bfloat16 g_wothi[(size_t)DD * DD];    // [n][k] wo
__device__ __align__(16) __nv_bfloat16 g_wotlo[(size_t)DD * DD];

extern __shared__ char dyn_smem[];

// ---------------------------------------------------------------------------
// PTX helpers (family-portable: cp.async / ldmatrix / mma.sync)
// ---------------------------------------------------------------------------
__device__ __forceinline__ uint32_t smem_u32(const void* p) {
    uint32_t a;
    asm("{ .reg .u64 t; cvta.to.shared.u64 t, %1; cvt.u32.u64 %0, t; }"
        : "=r"(a) : "l"(p));
    return a;
}

__device__ __forceinline__ void cp16(uint32_t dst, const void* src) {
    asm volatile("cp.async.cg.shared.global [%0], [%1], 16;" :: "r"(dst), "l"(src));
}
#define CP_COMMIT() asm volatile("cp.async.commit_group;" ::: "memory")
#define CP_WAIT(N)  asm volatile("cp.async.wait_group %0;" :: "n"(N) : "memory")

__device__ __forceinline__ void ldsm4(uint32_t* r, uint32_t a) {
    asm volatile("ldmatrix.sync.aligned.m8n8.x4.shared.b16 {%0,%1,%2,%3}, [%4];"
        : "=r"(r[0]), "=r"(r[1]), "=r"(r[2]), "=r"(r[3]) : "r"(a));
}
__device__ __forceinline__ void ldsm4t(uint32_t* r, uint32_t a) {
    asm volatile("ldmatrix.sync.aligned.m8n8.x4.trans.shared.b16 {%0,%1,%2,%3}, [%4];"
        : "=r"(r[0]), "=r"(r[1]), "=r"(r[2]), "=r"(r[3]) : "r"(a));
}

__device__ __forceinline__ void mma_bf16(float* c, const uint32_t* a, const uint32_t* b) {
    asm volatile(
        "mma.sync.aligned.m16n8k16.row.col.f32.bf16.bf16.f32 "
        "{%0,%1,%2,%3}, {%4,%5,%6,%7}, {%8,%9}, {%0,%1,%2,%3};"
        : "+f"(c[0]), "+f"(c[1]), "+f"(c[2]), "+f"(c[3])
        : "r"(a[0]), "r"(a[1]), "r"(a[2]), "r"(a[3]), "r"(b[0]), "r"(b[1]));
}

__device__ __forceinline__ uint32_t pack_bf2(float x, float y) {
    __nv_bfloat162 t;
    t.x = __float2bfloat16(x);
    t.y = __float2bfloat16(y);
    return *(uint32_t*)&t;
}

// ---------------------------------------------------------------------------
// Conversion kernels
// ---------------------------------------------------------------------------
__global__ void __launch_bounds__(256) transpose_convert_kernel(
    const float* __restrict__ src, int R, int C, int row_off, int which)
{
    __shared__ float t[32][33];
    const int c0 = blockIdx.x * 32;
    const int r0 = blockIdx.y * 32;
    const int tx = threadIdx.x;     // 0..31
    const int ty = threadIdx.y;     // 0..7

#pragma unroll
    for (int j = 0; j < 4; j++)
        t[ty + j * 8][tx] = src[(size_t)(r0 + ty + j * 8) * C + c0 + tx];
    __syncthreads();

    __nv_bfloat16* dhi = which ? g_wothi : g_wthi;
    __nv_bfloat16* dlo = which ? g_wotlo : g_wtlo;
#pragma unroll
    for (int j = 0; j < 4; j++) {
        const int i = ty + j * 8;
        const float v = t[tx][i];
        const __nv_bfloat16 h = __float2bfloat16(v);
        const __nv_bfloat16 l = __float2bfloat16(v - __bfloat162float(h));
        const size_t off = (size_t)(row_off + c0 + i) * DD + r0 + tx;
        dhi[off] = h;
        dlo[off] = l;
    }
}

__global__ void __launch_bounds__(256) convert_split_x_kernel(const float* __restrict__ src)
{
    const size_t i = (size_t)blockIdx.x * blockDim.x + threadIdx.x;
    const size_t n4 = (size_t)TOK * DD / 4;
    if (i >= n4) return;
    const float4 v = ((const float4*)src)[i];
    __nv_bfloat16 h0 = __float2bfloat16(v.x);
    __nv_bfloat16 h1 = __float2bfloat16(v.y);
    __nv_bfloat16 h2 = __float2bfloat16(v.z);
    __nv_bfloat16 h3 = __float2bfloat16(v.w);
    uint2 hp, lp;
    hp.x = pack_bf2(v.x, v.y);
    hp.y = pack_bf2(v.z, v.w);
    lp.x = pack_bf2(v.x - __bfloat162float(h0), v.y - __bfloat162float(h1));
    lp.y = pack_bf2(v.z - __bfloat162float(h2), v.w - __bfloat162float(h3));
    ((uint2*)g_xhi)[i] = hp;
    ((uint2*)g_xlo)[i] = lp;
}

// ---------------------------------------------------------------------------
// split-bf16 warp-MMA GEMM (unchanged from R3): C = A * B^T
// ---------------------------------------------------------------------------
#define BK 32
#define PITCH 80
#define MAT_BYTES (128 * PITCH)           // 10240
#define STAGE_BYTES (4 * MAT_BYTES)       // 40960
#define GEMM_SMEM_BYTES (2 * STAGE_BYTES) // 81920

__device__ __forceinline__ void prefetch_stage(
    uint32_t sbase,
    const __nv_bfloat16* __restrict__ Ahi, const __nv_bfloat16* __restrict__ Alo,
    const __nv_bfloat16* __restrict__ Bhi, const __nv_bfloat16* __restrict__ Blo,
    int m0, int n0, int k0, int ldA, int ldB, int tid)
{
#pragma unroll
    for (int j = 0; j < 2; j++) {
        const int id = tid * 2 + j;          // 0..511
        const int r = id >> 2;               // row 0..127
        const int c = id & 3;                // 16B chunk 0..3
        const uint32_t soff = r * PITCH + c * 16;
        const size_t ga = (size_t)(m0 + r) * ldA + k0 + c * 8;
        const size_t gb = (size_t)(n0 + r) * ldB + k0 + c * 8;
        cp16(sbase + soff,                 Ahi + ga);
        cp16(sbase + MAT_BYTES + soff,     Alo + ga);
        cp16(sbase + 2 * MAT_BYTES + soff, Bhi + gb);
        cp16(sbase + 3 * MAT_BYTES + soff, Blo + gb);
    }
}

__device__ __forceinline__ void gemm_bf16x3_body(
    const __nv_bfloat16* __restrict__ Ahi, const __nv_bfloat16* __restrict__ Alo,
    const __nv_bfloat16* __restrict__ Bhi, const __nv_bfloat16* __restrict__ Blo,
    float* __restrict__ Cc, int K, int ldA, int ldB, int ldC)
{
    const int tid  = threadIdx.x;           // 256 threads
    const int lane = tid & 31;
    const int wid  = tid >> 5;               // 0..7
    const int wm   = wid & 1;                // 2 m-warps
    const int wn   = wid >> 1;               // 4 n-warps
    const int m0   = blockIdx.y * 128;
    const int n0   = blockIdx.x * 128;
    const uint32_t smem_base = smem_u32(dyn_smem);

    float c[4][4][4];
#pragma unroll
    for (int i = 0; i < 4; i++)
#pragma unroll
        for (int j = 0; j < 4; j++)
#pragma unroll
            for (int k = 0; k < 4; k++) c[i][j][k] = 0.f;

    const uint32_t a_lane_off =
        (uint32_t)((wm * 64 + (lane & 15)) * PITCH + (lane >> 4) * 16);
    const uint32_t b_lane_off =
        (uint32_t)((wn * 32 + (lane & 7) + ((lane >> 4) << 3)) * PITCH +
                   ((lane >> 3) & 1) * 16);

    const int nk = K / BK;    // 64

    prefetch_stage(smem_base, Ahi, Alo, Bhi, Blo, m0, n0, 0, ldA, ldB, tid);
    CP_COMMIT();

    for (int it = 0; it < nk; it++) {
        CP_WAIT(0);
        __syncthreads();

        if (it + 1 < nk) {
            prefetch_stage(smem_base + ((it + 1) & 1) * STAGE_BYTES,
                           Ahi, Alo, Bhi, Blo, m0, n0, (it + 1) * BK, ldA, ldB, tid);
            CP_COMMIT();
        }

        const uint32_t sA = smem_base + (it & 1) * STAGE_BYTES;
        const uint32_t sB = sA + 2 * MAT_BYTES;

#pragma unroll
        for (int kf = 0; kf < 2; kf++) {
            uint32_t a[2][4][4];
            uint32_t b[2][2][4];
#pragma unroll
            for (int mf = 0; mf < 4; mf++) {
                const uint32_t ad = sA + a_lane_off + mf * 16 * PITCH + kf * 32;
                ldsm4(a[0][mf], ad);
                ldsm4(a[1][mf], ad + MAT_BYTES);
            }
#pragma unroll
            for (int nf2 = 0; nf2 < 2; nf2++) {
                const uint32_t bd = sB + b_lane_off + nf2 * 16 * PITCH + kf * 32;
                ldsm4(b[0][nf2], bd);
                ldsm4(b[1][nf2], bd + MAT_BYTES);
            }
#pragma unroll
            for (int mf = 0; mf < 4; mf++)
#pragma unroll
                for (int nf = 0; nf < 4; nf++) {
                    float* cc = c[mf][nf];
                    const uint32_t* bh = &b[0][nf >> 1][(nf & 1) * 2];
                    const uint32_t* bl = &b[1][nf >> 1][(nf & 1) * 2];
                    mma_bf16(cc, a[0][mf], bh);   // hi*hi
                    mma_bf16(cc, a[0][mf], bl);   // hi*lo
                    mma_bf16(cc, a[1][mf], bh);   // lo*hi
                }
        }
    }

    const int row0 = m0 + wm * 64;
    const int col0 = n0 + wn * 32;
    const int gr = lane >> 2;
    const int gc = (lane & 3) * 2;
#pragma unroll
    for (int mf = 0; mf < 4; mf++)
#pragma unroll
        for (int nf = 0; nf < 4; nf++) {
            float* cc = c[mf][nf];
            const int r = row0 + mf * 16 + gr;
            const int cl = col0 + nf * 8 + gc;
            *(float2*)&Cc[(size_t)r * ldC + cl]       = make_float2(cc[0], cc[1]);
            *(float2*)&Cc[(size_t)(r + 8) * ldC + cl] = make_float2(cc[2], cc[3]);
        }
}

__global__ void __launch_bounds__(256) gemm_qkv_kernel() {
    gemm_bf16x3_body(g_xhi, g_xlo, g_wthi, g_wtlo, g_qkv, DD, DD, DD, QKVW);
}
__global__ void __launch_bounds__(256) gemm_out_kernel(float* __restrict__ out) {
    gemm_bf16x3_body(g_ohi, g_olo, g_wothi, g_wotlo, out, DD, DD, DD, DD);
}

// ---------------------------------------------------------------------------
// RMSNorm + RoPE + bf16 hi/lo split. One warp per 128-vector.
//   q: norm+rope, pre-scaled by (1/sqrt(H))*log2(e), split -> g_qhi/g_qlo
//   k: norm+rope, split -> g_khi/g_klo
//   v: straight split -> g_vhi/g_vlo
// ---------------------------------------------------------------------------
__global__ void __launch_bounds__(256) norm_rope_split_kernel(
    const int* __restrict__ pos_ids,
    const float* __restrict__ q_norm_w,
    const float* __restrict__ k_norm_w)
{
    const int warp = (blockIdx.x * blockDim.x + threadIdx.x) >> 5;
    const int lane = threadIdx.x & 31;
    const int NQ = TOK * NHEADS;
    const int NK = TOK * KHEADS;

    // --- V path: straight split, no norm/rope ---
    if (warp >= NQ + NK) {
        const int idx = warp - NQ - NK;
        if (idx >= TOK * KHEADS) return;
        const int token = idx >> 3;
        const int kh = idx & 7;
        const float* src = g_qkv + (size_t)token * QKVW + 3072 + kh * HDIM + lane * 4;
        const float4 v = *(const float4*)src;
        __nv_bfloat16 h0 = __float2bfloat16(v.x);
        __nv_bfloat16 h1 = __float2bfloat16(v.y);
        __nv_bfloat16 h2 = __float2bfloat16(v.z);
        __nv_bfloat16 h3 = __float2bfloat16(v.w);
        uint2 hp, lp;
        hp.x = pack_bf2(v.x, v.y);
        hp.y = pack_bf2(v.z, v.w);
        lp.x = pack_bf2(v.x - __bfloat162float(h0), v.y - __bfloat162float(h1));
        lp.y = pack_bf2(v.z - __bfloat162float(h2), v.w - __bfloat162float(h3));
        const size_t off = (size_t)token * 1024 + kh * HDIM + lane * 4;
        *(uint2*)&g_vhi[off] = hp;
        *(uint2*)&g_vlo[off] = lp;
        return;
    }

    const bool isq = warp < NQ;
    int token, hidx;
    const float* vecsrc;
    const float* w;
    if (isq) {
        token = warp >> 4;
        hidx = warp & 15;
        vecsrc = g_qkv + (size_t)token * QKVW + hidx * HDIM;
        w = q_norm_w;
    } else {
        const int kv = warp - NQ;
        token = kv >> 3;
        hidx = kv & 7;
        vecsrc = g_qkv + (size_t)token * QKVW + 2048 + hidx * HDIM;
        w = k_norm_w;
    }
    const int pos = pos_ids[token];

    float4 x4 = *(const float4*)&vecsrc[lane * 4];
    float ss = x4.x * x4.x + x4.y * x4.y + x4.z * x4.z + x4.w * x4.w;
#pragma unroll
    for (int m = 16; m; m >>= 1) ss += __shfl_xor_sync(0xffffffffu, ss, m);
    const float rinv = rsqrtf(ss * (1.0f / HDIM) + EPSV);

    float4 w4 = *(const float4*)&w[lane * 4];
    float n0 = x4.x * w4.x * rinv;
    float n1 = x4.y * w4.y * rinv;
    float n2 = x4.z * w4.z * rinv;
    float n3 = x4.w * w4.w * rinv;

    float p0 = __shfl_xor_sync(0xffffffffu, n0, 16);
    float p1 = __shfl_xor_sync(0xffffffffu, n1, 16);
    float p2 = __shfl_xor_sync(0xffffffffu, n2, 16);
    float p3 = __shfl_xor_sync(0xffffffffu, n3, 16);

    const bool firsthalf = lane < 16;
    const int pbase = (lane & 15) * 4;
    const float fpos = (float)pos;
    const double L2T = 19.931568569324174;   // log2(1e6)
    // scale * log2(e) folded into q so softmax runs in exp2 domain
    const float QS = isq ? 0.08838834764831845f * 1.4426950408889634f : 1.0f;

    float nv[4] = {n0, n1, n2, n3};
    float pv[4] = {p0, p1, p2, p3};
    float res[4];
#pragma unroll
    for (int j = 0; j < 4; j++) {
        const int p = pbase + j;
        const float inv_ts = exp2f((float)(-(double)p * L2T / 64.0));
        const float ang = fpos * inv_ts;
        float sv, cv;
        sincosf(ang, &sv, &cv);
        const float r = firsthalf ? (nv[j] * cv - pv[j] * sv)
                                  : (nv[j] * cv + pv[j] * sv);
        res[j] = r * QS;
    }

    __nv_bfloat16 h0 = __float2bfloat16(res[0]);
    __nv_bfloat16 h1 = __float2bfloat16(res[1]);
    __nv_bfloat16 h2 = __float2bfloat16(res[2]);
    __nv_bfloat16 h3 = __float2bfloat16(res[3]);
    uint2 hp, lp;
    hp.x = pack_bf2(res[0], res[1]);
    hp.y = pack_bf2(res[2], res[3]);
    lp.x = pack_bf2(res[0] - __bfloat162float(h0), res[1] - __bfloat162float(h1));
    lp.y = pack_bf2(res[2] - __bfloat162float(h2), res[3] - __bfloat162float(h3));

    if (isq) {
        const size_t off = (size_t)token * 2048 + hidx * HDIM + lane * 4;
        *(uint2*)&g_qhi[off] = hp;
        *(uint2*)&g_qlo[off] = lp;
    } else {
        const size_t off = (size_t)token * 1024 + hidx * HDIM + lane * 4;
        *(uint2*)&g_khi[off] = hp;
        *(uint2*)&g_klo[off] = lp;
    }
}

// ---------------------------------------------------------------------------
// Flash attention on tensor cores (mma.sync bf16, split x3).
//   Block: 128 q-rows x (head n, batch b). 8 warps, warp = 16 q-rows.
//   KV tiles of 64, double-buffered cp.async.
//   SMEM: Qhi/Qlo [128][128] resident + 2 stages of {Khi,Klo,Vhi,Vlo}[64][128].
//   Row pitch 272B (128 bf16 + 8 pad) -> conflict-free ldmatrix.
// ---------------------------------------------------------------------------
#define FLP 272
#define FL_QSZ (128 * FLP)          // 34816
#define FL_KVSZ (64 * FLP)          // 17408
#define FL_STAGE (4 * FL_KVSZ)      // 69632
#define FL_SMEM (2 * FL_QSZ + 2 * FL_STAGE)   // 208896

__device__ __forceinline__ void fl_prefetch_kv(
    uint32_t sbase, int b, int kvh, int kv0, int tid)
{
#pragma unroll
    for (int u = 0; u < 16; u++) {
        const int mtx = u >> 2;                      // 0:Khi 1:Klo 2:Vhi 3:Vlo
        const int row = ((u & 3) << 4) + (tid >> 4); // 0..63
        const int ch = tid & 15;
        const __nv_bfloat16* g;
        if (mtx == 0)      g = g_khi;
        else if (mtx == 1) g = g_klo;
        else if (mtx == 2) g = g_vhi;
        else               g = g_vlo;
        g += (size_t)(b * LL + kv0 + row) * 1024 + kvh * HDIM + ch * 8;
        cp16(sbase + mtx * FL_KVSZ + row * FLP + ch * 16, g);
    }
}

__global__ void __launch_bounds__(256, 1) flash_kernel()
{
    const int tid = threadIdx.x;
    const int lane = tid & 31;
    const int wid = tid >> 5;
    const int b = blockIdx.z;
    const int n = blockIdx.y;
    const int mt = (int)gridDim.x - 1 - (int)blockIdx.x;  // big tiles launch first
    const int kvh = n >> 1;
    const int m0 = mt * 128;

    const uint32_t sb = smem_u32(dyn_smem);
    const uint32_t sQhi = sb;
    const uint32_t sQlo = sb + FL_QSZ;
    const uint32_t sStage0 = sb + 2 * FL_QSZ;

    // load Q hi/lo (cp.async)
#pragma unroll
    for (int u = 0; u < 16; u++) {
        const int mtx = u >> 3;
        const int row = ((u & 7) << 4) + (tid >> 4);
        const int ch = tid & 15;
        const __nv_bfloat16* g = (mtx ? g_qlo : g_qhi) +
            (size_t)(b * LL + m0 + row) * 2048 + n * HDIM + ch * 8;
        cp16((mtx ? sQlo : sQhi) + row * FLP + ch * 16, g);
    }
    fl_prefetch_kv(sStage0, b, kvh, 0, tid);
    CP_COMMIT();

    float acc[16][4];
#pragma unroll
    for (int i = 0; i < 16; i++)
#pragma unroll
        for (int j = 0; j < 4; j++) acc[i][j] = 0.f;
    float m2[2] = {-1e30f, -1e30f};
    float lsum[2] = {0.f, 0.f};

    const uint32_t a_off = (uint32_t)((wid * 16 + (lane & 15)) * FLP + (lane >> 4) * 16);
    const uint32_t bk_off = (uint32_t)(((lane & 7) + ((lane >> 4) << 3)) * FLP +
                                       ((lane >> 3) & 1) * 16);
    const uint32_t v_off = (uint32_t)(((lane & 7) + ((lane >> 3) & 1) * 8) * FLP +
                                      (lane >> 4) * 16);

    const int nkv = 2 * (mt + 1);
    for (int it = 0; it < nkv; it++) {
        CP_WAIT(0);
        __syncthreads();
        if (it + 1 < nkv) {
            fl_prefetch_kv(sStage0 + ((it + 1) & 1) * FL_STAGE, b, kvh, (it + 1) * 64, tid);
            CP_COMMIT();
        }
        const uint32_t sKhi = sStage0 + (it & 1) * FL_STAGE;
        const uint32_t sKlo = sKhi + FL_KVSZ;
        const uint32_t sVhi = sKhi + 2 * FL_KVSZ;
        const uint32_t sVlo = sKhi + 3 * FL_KVSZ;

        // --- S = Q K^T (scores in exp2 domain; q pre-scaled) ---
        float sfr[8][4];
#pragma unroll
        for (int i = 0; i < 8; i++)
#pragma unroll
            for (int j = 0; j < 4; j++) sfr[i][j] = 0.f;

#pragma unroll
        for (int kf = 0; kf < 8; kf++) {
            uint32_t ah[4], al[4];
            ldsm4(ah, sQhi + a_off + kf * 32);
            ldsm4(al, sQlo + a_off + kf * 32);
#pragma unroll
            for (int p2 = 0; p2 < 4; p2++) {
                uint32_t bh[4], bl[4];
                ldsm4(bh, sKhi + bk_off + p2 * 16 * FLP + kf * 32);
                ldsm4(bl, sKlo + bk_off + p2 * 16 * FLP + kf * 32);
                mma_bf16(sfr[2 * p2], ah, bh);
                mma_bf16(sfr[2 * p2], ah, bl);
                mma_bf16(sfr[2 * p2], al, bh);
                mma_bf16(sfr[2 * p2 + 1], ah, bh + 2);
                mma_bf16(sfr[2 * p2 + 1], ah, bl + 2);
                mma_bf16(sfr[2 * p2 + 1], al, bh + 2);
            }
        }

        // --- causal mask (only near-diagonal tiles) ---
        const int rbase = m0 + wid * 16 + (lane >> 2);
        if (it * 64 + 63 > m0 + wid * 16) {
#pragma unroll
            for (int nf = 0; nf < 8; nf++) {
                const int cg = it * 64 + nf * 8 + 2 * (lane & 3);
#pragma unroll
                for (int rg = 0; rg < 4; rg++) {
                    const int row = rbase + (rg >> 1) * 8;
                    const int col = cg + (rg & 1);
                    if (col > row) sfr[nf][rg] = -1e30f;
                }
            }
        }

        // --- online softmax (exp2 domain), warp-local rows ---
#pragma unroll
        for (int h = 0; h < 2; h++) {
            float tm = -1e30f;
#pragma unroll
            for (int nf = 0; nf < 8; nf++)
                tm = fmaxf(tm, fmaxf(sfr[nf][2 * h], sfr[nf][2 * h + 1]));
            tm = fmaxf(tm, __shfl_xor_sync(0xffffffffu, tm, 1));
            tm = fmaxf(tm, __shfl_xor_sync(0xffffffffu, tm, 2));
            const float mn = fmaxf(m2[h], tm);
            const float corr = exp2f(m2[h] - mn);
            m2[h] = mn;
            float rs = 0.f;
#pragma unroll
            for (int nf = 0; nf < 8; nf++) {
                const float e0 = exp2f(sfr[nf][2 * h] - mn);
                const float e1 = exp2f(sfr[nf][2 * h + 1] - mn);
                sfr[nf][2 * h] = e0;
                sfr[nf][2 * h + 1] = e1;
                rs += e0 + e1;
            }
            rs += __shfl_xor_sync(0xffffffffu, rs, 1);
            rs += __shfl_xor_sync(0xffffffffu, rs, 2);
            lsum[h] = lsum[h] * corr + rs;
#pragma unroll
            for (int nf = 0; nf < 16; nf++) {
                acc[nf][2 * h] *= corr;
                acc[nf][2 * h + 1] *= corr;
            }
        }

        // --- O += P V (P frags built from S frags; classic layout identity) ---
#pragma unroll
        for (int j = 0; j < 4; j++) {
            uint32_t ph[4], pl[4];
#pragma unroll
            for (int q = 0; q < 4; q++) {
                const int nf = 2 * j + (q >> 1);
                const int rb = (q & 1) * 2;
                const float v0 = sfr[nf][rb], v1 = sfr[nf][rb + 1];
                const __nv_bfloat16 h0 = __float2bfloat16(v0);
                const __nv_bfloat16 h1 = __float2bfloat16(v1);
                ph[q] = pack_bf2(v0, v1);
                pl[q] = pack_bf2(v0 - __bfloat162float(h0), v1 - __bfloat162float(h1));
            }
#pragma unroll
            for (int t = 0; t < 8; t++) {
                uint32_t vh[4], vl[4];
                ldsm4t(vh, sVhi + v_off + j * 16 * FLP + t * 32);
                ldsm4t(vl, sVlo + v_off + j * 16 * FLP + t * 32);
                mma_bf16(acc[2 * t], ph, vh);
                mma_bf16(acc[2 * t], ph, vl);
                mma_bf16(acc[2 * t], pl, vh);
                mma_bf16(acc[2 * t + 1], ph, vh + 2);
                mma_bf16(acc[2 * t + 1], ph, vl + 2);
                mma_bf16(acc[2 * t + 1], pl, vh + 2);
            }
        }
    }

    // --- finalize: /l, split to bf16 hi/lo, store ---
#pragma unroll
    for (int h = 0; h < 2; h++) {
        const float inv = 1.0f / lsum[h];
        const int row = m0 + wid * 16 + (lane >> 2) + h * 8;
        const size_t base = (size_t)(b * LL + row) * 2048 + n * HDIM + 2 * (lane & 3);
#pragma unroll
        for (int nf = 0; nf < 16; nf++) {
            const float v0 = acc[nf][2 * h] * inv;
            const float v1 = acc[nf][2 * h + 1] * inv;
            const __nv_bfloat16 h0 = __float2bfloat16(v0);
            const __nv_bfloat16 h1 = __float2bfloat16(v1);
            *(uint32_t*)&g_ohi[base + nf * 8] = pack_bf2(v0, v1);
            *(uint32_t*)&g_olo[base + nf * 8] =
                pack_bf2(v0 - __bfloat162float(h0), v1 - __bfloat162float(h1));
        }
    }
}

// ---------------------------------------------------------------------------
// Launch
// ---------------------------------------------------------------------------
extern "C" void kernel_launch(void* const* d_in, const int* in_sizes, int n_in,
                              void* d_out, int out_size)
{
    const float* x   = (const float*)d_in[0];
    const int*   pos = (const int*)d_in[1];
    // d_in[2] = attn_mask (causal tril) — implied analytically, unused
    const float* wq  = (const float*)d_in[3];
    const float* wk  = (const float*)d_in[4];
    const float* wv  = (const float*)d_in[5];
    const float* wo  = (const float*)d_in[6];
    const float* qnw = (const float*)d_in[7];
    const float* knw = (const float*)d_in[8];
    float* out = (float*)d_out;

    cudaFuncSetAttribute(gemm_qkv_kernel,
                         cudaFuncAttributeMaxDynamicSharedMemorySize, GEMM_SMEM_BYTES);
    cudaFuncSetAttribute(gemm_out_kernel,
                         cudaFuncAttributeMaxDynamicSharedMemorySize, GEMM_SMEM_BYTES);
    cudaFuncSetAttribute(flash_kernel,
                         cudaFuncAttributeMaxDynamicSharedMemorySize, FL_SMEM);

    // 1. weights -> transposed bf16 hi/lo
    transpose_convert_kernel<<<dim3(64, 64), dim3(32, 8)>>>(wq, 2048, 2048, 0, 0);
    transpose_convert_kernel<<<dim3(32, 64), dim3(32, 8)>>>(wk, 2048, 1024, 2048, 0);
    transpose_convert_kernel<<<dim3(32, 64), dim3(32, 8)>>>(wv, 2048, 1024, 3072, 0);
    transpose_convert_kernel<<<dim3(64, 64), dim3(32, 8)>>>(wo, 2048, 2048, 0, 1);

    // 2. split X
    convert_split_x_kernel<<<(TOK * DD / 4 + 255) / 256, 256>>>(x);

    // 3. QKV projection
    gemm_qkv_kernel<<<dim3(QKVW / 128, TOK / 128), 256, GEMM_SMEM_BYTES>>>();

    // 4. RMSNorm + RoPE + split (q,k,v)
    {
        const int nwarps = TOK * (NHEADS + 2 * KHEADS);   // 131072
        const int blocks = nwarps * 32 / 256;
        norm_rope_split_kernel<<<blocks, 256>>>(pos, qnw, knw);
    }

    // 5. Flash attention (tensor cores)
    flash_kernel<<<dim3(LL / 128, NHEADS, BB), 256, FL_SMEM>>>();

    // 6. output projection
    gemm_out_kernel<<<dim3(DD / 128, TOK / 128), 256, GEMM_SMEM_BYTES>>>(out);
}